// round 8
// baseline (speedup 1.0000x reference)
#include <cuda_runtime.h>
#include <cuda_bf16.h>

#define N_NODES   4000000
#define N_GRAPHS  4096
#define D_FEAT    8
#define N_CLASSES 10
#define WARPS_PER_BLOCK 4
#define N_BLOCKS (N_GRAPHS / WARPS_PER_BLOCK)
#define FULL 0xFFFFFFFFu

// batch_ids may be int64 OR int32 (JAX under default x64=False silently makes
// them int32). Values < 4096, so for int64 data every high word is 0: viewing
// the buffer as int32, element N_NODES-1 is an int64 high word (==0) or the
// max sorted int32 id (>0).
__device__ __forceinline__ int id_at(const int* __restrict__ ids32, bool is64, int i) {
    return is64 ? ids32[2 * i] : ids32[i];
}

// Half-warp cooperative 16-ary lower_bound of v over sorted ids in [lo, hi).
__device__ __forceinline__ int kary_lower_bound(
    const int* __restrict__ ids32, bool is64, int v,
    int lo, int hi, int sub, int half_shift)
{
    const unsigned hmask = 0xFFFFu << half_shift;
    while (hi - lo > 16) {
        const int range = hi - lo;
        const int pos = lo + (int)(((long long)range * (sub + 1)) >> 4);
        const bool less = id_at(ids32, is64, pos - 1) < v;
        const unsigned ball = __ballot_sync(hmask, less);
        const int cnt = __popc((ball >> half_shift) & 0xFFFFu);
        const int nlo = lo + (int)(((long long)range * cnt) >> 4);
        const int nhi = (cnt == 16) ? hi
                      : lo + (int)(((long long)range * (cnt + 1)) >> 4);
        lo = nlo; hi = nhi;
    }
    const int pos = lo + sub;
    const bool less = (pos < hi) ? (id_at(ids32, is64, pos) < v) : false;
    const unsigned ball = __ballot_sync(hmask, less);
    return lo + __popc((ball >> half_shift) & 0xFFFFu);
}

#define ACC4(A, V) do { A.x += V.x; A.y += V.y; A.z += V.z; A.w += V.w; } while (0)

// min-blocks=1: let ptxas allocate enough registers that all 12 in-flight
// float4 loads get DISTINCT destination registers (MLP_eff == 12, no
// scoreboard waits inside the batch). Grid supplies only ~28 warps/SM, so
// high reg count costs no residency.
__global__ __launch_bounds__(128, 1) void fused_pool_gemm_kernel(
    const float4* __restrict__ x4,
    const int*    __restrict__ ids32,
    const float*  __restrict__ W,      // [10, 8]
    const float*  __restrict__ b,      // [10]
    float*        __restrict__ out)    // [4096, 10]
{
    const int warp = threadIdx.x >> 5;
    const int lane = threadIdx.x & 31;
    const int g    = blockIdx.x * WARPS_PER_BLOCK + warp;   // segment id

    // ---- Phase 0: L2 prefetch of segment head while the search runs ----
    {
        long long arow = ((long long)g * N_NODES) >> 12;
        if (arow > N_NODES - 512) arow = N_NODES - 512;
        const char* pbase = (const char*)x4 + arow * 32 + (long long)lane * 128;
        #pragma unroll
        for (int k = 0; k < 4; k++)
            asm volatile("prefetch.global.L2 [%0];" :: "l"(pbase + k * 4096));
    }

    // ---- Phase 1: per-warp cooperative boundary search ----
    const bool is64 = (ids32[N_NODES - 1] == 0);
    const int half_shift = lane & 16;
    const int sub = lane & 15;
    const int v = (half_shift == 0) ? g : g + 1;

    int res;
    if (v >= N_GRAPHS) {
        res = N_NODES;
    } else {
        const long long approx = ((long long)v * N_NODES) >> 12;
        int lo = (int)(approx - 8192); if (lo < 0) lo = 0;
        int hi = (int)(approx + 8192); if (hi > N_NODES) hi = N_NODES;
        const bool ok_lo = (lo == 0)       || (id_at(ids32, is64, lo - 1) < v);
        const bool ok_hi = (hi == N_NODES) || (id_at(ids32, is64, hi) >= v);
        if (!(ok_lo && ok_hi)) { lo = 0; hi = N_NODES; }
        res = kary_lower_bound(ids32, is64, v, lo, hi, sub, half_shift);
    }
    __syncwarp(FULL);
    const int start = __shfl_sync(FULL, res, 0);
    const int end   = __shfl_sync(FULL, res, 16);
    const int cnt   = end - start;
    const long long base = (long long)start * 2;   // float4 units
    const int n4 = cnt * 2;

    // ---- Phase 2: float4 streaming reduction, 12 independent loads/iter ----
    float4 acc0 = make_float4(0.f,0.f,0.f,0.f);
    float4 acc1 = make_float4(0.f,0.f,0.f,0.f);
    float4 acc2 = make_float4(0.f,0.f,0.f,0.f);
    float4 acc3 = make_float4(0.f,0.f,0.f,0.f);

    int c = 0;
    while (c + 384 <= n4) {     // 12 loads x 32 lanes
        const long long p = base + c + lane;
        float4 v0  = __ldg(&x4[p       ]);
        float4 v1  = __ldg(&x4[p +  32 ]);
        float4 v2  = __ldg(&x4[p +  64 ]);
        float4 v3  = __ldg(&x4[p +  96 ]);
        float4 v4  = __ldg(&x4[p + 128 ]);
        float4 v5  = __ldg(&x4[p + 160 ]);
        float4 v6  = __ldg(&x4[p + 192 ]);
        float4 v7  = __ldg(&x4[p + 224 ]);
        float4 v8  = __ldg(&x4[p + 256 ]);
        float4 v9  = __ldg(&x4[p + 288 ]);
        float4 v10 = __ldg(&x4[p + 320 ]);
        float4 v11 = __ldg(&x4[p + 352 ]);
        ACC4(acc0, v0);  ACC4(acc1, v1);  ACC4(acc2, v2);  ACC4(acc3, v3);
        ACC4(acc0, v4);  ACC4(acc1, v5);  ACC4(acc2, v6);  ACC4(acc3, v7);
        ACC4(acc0, v8);  ACC4(acc1, v9);  ACC4(acc2, v10); ACC4(acc3, v11);
        c += 384;
    }
    for (int j = c + lane; j < n4; j += 32) {
        float4 vv = __ldg(&x4[base + j]);
        ACC4(acc0, vv);
    }
    acc0.x += acc1.x + acc2.x + acc3.x;
    acc0.y += acc1.y + acc2.y + acc3.y;
    acc0.z += acc1.z + acc2.z + acc3.z;
    acc0.w += acc1.w + acc2.w + acc3.w;

    // Parity-preserving butterfly: lane 0 -> cols 0-3, lane 1 -> cols 4-7.
    #pragma unroll
    for (int m = 16; m >= 2; m >>= 1) {
        acc0.x += __shfl_xor_sync(FULL, acc0.x, m);
        acc0.y += __shfl_xor_sync(FULL, acc0.y, m);
        acc0.z += __shfl_xor_sync(FULL, acc0.z, m);
        acc0.w += __shfl_xor_sync(FULL, acc0.w, m);
    }

    // ---- Phase 3: broadcast pooled vector via shuffles, fused tiny GEMM ----
    const float inv = (cnt > 0) ? (1.0f / (float)cnt) : 0.0f;
    const float p0 = __shfl_sync(FULL, acc0.x, 0) * inv;
    const float p1 = __shfl_sync(FULL, acc0.y, 0) * inv;
    const float p2 = __shfl_sync(FULL, acc0.z, 0) * inv;
    const float p3 = __shfl_sync(FULL, acc0.w, 0) * inv;
    const float p4 = __shfl_sync(FULL, acc0.x, 1) * inv;
    const float p5 = __shfl_sync(FULL, acc0.y, 1) * inv;
    const float p6 = __shfl_sync(FULL, acc0.z, 1) * inv;
    const float p7 = __shfl_sync(FULL, acc0.w, 1) * inv;

    if (lane < N_CLASSES) {
        const float* w = W + lane * D_FEAT;
        float r = __ldg(&b[lane]);
        r += p0 * __ldg(&w[0]) + p1 * __ldg(&w[1]) + p2 * __ldg(&w[2]) + p3 * __ldg(&w[3]);
        r += p4 * __ldg(&w[4]) + p5 * __ldg(&w[5]) + p6 * __ldg(&w[6]) + p7 * __ldg(&w[7]);
        out[g * N_CLASSES + lane] = r;
    }
}

extern "C" void kernel_launch(void* const* d_in, const int* in_sizes, int n_in,
                              void* d_out, int out_size) {
    // Bind inputs by element count (robust to metadata ordering):
    //   x: 32,000,000 f32 | batch_ids: 4,000,000 | W: 80 | b: 10
    const float* x   = nullptr;
    const void*  ids = nullptr;
    const float* W   = nullptr;
    const float* b   = nullptr;
    for (int i = 0; i < n_in; i++) {
        switch (in_sizes[i]) {
            case N_NODES * D_FEAT:   x   = (const float*)d_in[i]; break;
            case N_NODES:            ids = d_in[i];               break;
            case N_CLASSES * D_FEAT: W   = (const float*)d_in[i]; break;
            case N_CLASSES:          b   = (const float*)d_in[i]; break;
            default: break; // input_ids / attention_mask: unused
        }
    }
    float* out = (float*)d_out;

    fused_pool_gemm_kernel<<<N_BLOCKS, 128>>>(
        (const float4*)x, (const int*)ids, W, b, out);
}

// round 9
// speedup vs baseline: 1.0695x; 1.0695x over previous
#include <cuda_runtime.h>
#include <cuda_bf16.h>

#define N_NODES   4000000
#define N_GRAPHS  4096
#define D_FEAT    8
#define N_CLASSES 10
#define WARPS_PER_BLOCK 8
#define N_BLOCKS (N_GRAPHS / WARPS_PER_BLOCK)   // 512
#define FULL 0xFFFFFFFFu

// batch_ids may be int64 OR int32 (JAX under default x64=False silently makes
// them int32). Values < 4096, so for int64 data every high word is 0: viewing
// the buffer as int32, element N_NODES-1 is an int64 high word (==0) or the
// max sorted int32 id (>0).
__device__ __forceinline__ int id_at(const int* __restrict__ ids32, bool is64, int i) {
    return is64 ? ids32[2 * i] : ids32[i];
}

// Half-warp cooperative 16-ary lower_bound of v over sorted ids in [lo, hi).
__device__ __forceinline__ int kary_lower_bound(
    const int* __restrict__ ids32, bool is64, int v,
    int lo, int hi, int sub, int half_shift)
{
    const unsigned hmask = 0xFFFFu << half_shift;
    while (hi - lo > 16) {
        const int range = hi - lo;
        const int pos = lo + (int)(((long long)range * (sub + 1)) >> 4);
        const bool less = id_at(ids32, is64, pos - 1) < v;
        const unsigned ball = __ballot_sync(hmask, less);
        const int cnt = __popc((ball >> half_shift) & 0xFFFFu);
        const int nlo = lo + (int)(((long long)range * cnt) >> 4);
        const int nhi = (cnt == 16) ? hi
                      : lo + (int)(((long long)range * (cnt + 1)) >> 4);
        lo = nlo; hi = nhi;
    }
    const int pos = lo + sub;
    const bool less = (pos < hi) ? (id_at(ids32, is64, pos) < v) : false;
    const unsigned ball = __ballot_sync(hmask, less);
    return lo + __popc((ball >> half_shift) & 0xFFFFu);
}

// R2's winning stream shape: 256 threads, 8 warps = 8 segments per block,
// modest unroll, ~40-46 regs -> fully resident grid (512 blocks, 27.7 w/SM).
__global__ __launch_bounds__(256) void fused_pool_gemm_kernel(
    const float4* __restrict__ x4,
    const int*    __restrict__ ids32,
    const float*  __restrict__ W,      // [10, 8]
    const float*  __restrict__ b,      // [10]
    float*        __restrict__ out)    // [4096, 10]
{
    const int warp = threadIdx.x >> 5;
    const int lane = threadIdx.x & 31;
    const int g    = blockIdx.x * WARPS_PER_BLOCK + warp;   // segment id

    // ---- Phase 0: L2 prefetch of segment head; overlaps the search below ----
    {
        long long arow = ((long long)g * N_NODES) >> 12;
        if (arow > N_NODES - 512) arow = N_NODES - 512;
        const char* pbase = (const char*)x4 + arow * 32 + (long long)lane * 128;
        #pragma unroll
        for (int k = 0; k < 4; k++)
            asm volatile("prefetch.global.L2 [%0];" :: "l"(pbase + k * 4096));
    }

    // ---- Phase 1: per-warp cooperative boundary search (no block sync) ----
    const bool is64 = (ids32[N_NODES - 1] == 0);
    const int half_shift = lane & 16;
    const int sub = lane & 15;
    const int v = (half_shift == 0) ? g : g + 1;   // lower half: start; upper: end

    int res;
    if (v >= N_GRAPHS) {
        res = N_NODES;
    } else {
        // +-8192 window (>=8 sd of the binomial start position);
        // bracket-verified with full-range fallback.
        const long long approx = ((long long)v * N_NODES) >> 12;
        int lo = (int)(approx - 8192); if (lo < 0) lo = 0;
        int hi = (int)(approx + 8192); if (hi > N_NODES) hi = N_NODES;
        const bool ok_lo = (lo == 0)       || (id_at(ids32, is64, lo - 1) < v);
        const bool ok_hi = (hi == N_NODES) || (id_at(ids32, is64, hi) >= v);
        if (!(ok_lo && ok_hi)) { lo = 0; hi = N_NODES; }
        res = kary_lower_bound(ids32, is64, v, lo, hi, sub, half_shift);
    }
    __syncwarp(FULL);
    const int start = __shfl_sync(FULL, res, 0);
    const int end   = __shfl_sync(FULL, res, 16);
    const int cnt   = end - start;
    const long long base = (long long)start * 2;   // float4 units
    const int n4 = cnt * 2;

    // ---- Phase 2: float4 streaming reduction (R2 shape, unroll 4) ----
    float4 a0 = make_float4(0.f,0.f,0.f,0.f);
    float4 a1 = make_float4(0.f,0.f,0.f,0.f);

    int c = 0;
    while (c + 128 <= n4) {     // 4 loads x 32 lanes
        const long long p = base + c + lane;
        float4 v0 = __ldg(&x4[p     ]);
        float4 v1 = __ldg(&x4[p + 32]);
        float4 v2 = __ldg(&x4[p + 64]);
        float4 v3 = __ldg(&x4[p + 96]);
        a0.x += v0.x; a0.y += v0.y; a0.z += v0.z; a0.w += v0.w;
        a1.x += v1.x; a1.y += v1.y; a1.z += v1.z; a1.w += v1.w;
        a0.x += v2.x; a0.y += v2.y; a0.z += v2.z; a0.w += v2.w;
        a1.x += v3.x; a1.y += v3.y; a1.z += v3.z; a1.w += v3.w;
        c += 128;
    }
    for (int j = c + lane; j < n4; j += 32) {
        float4 vv = __ldg(&x4[base + j]);
        a0.x += vv.x; a0.y += vv.y; a0.z += vv.z; a0.w += vv.w;
    }
    a0.x += a1.x; a0.y += a1.y; a0.z += a1.z; a0.w += a1.w;

    // Parity-preserving butterfly: lane 0 -> cols 0-3, lane 1 -> cols 4-7.
    #pragma unroll
    for (int m = 16; m >= 2; m >>= 1) {
        a0.x += __shfl_xor_sync(FULL, a0.x, m);
        a0.y += __shfl_xor_sync(FULL, a0.y, m);
        a0.z += __shfl_xor_sync(FULL, a0.z, m);
        a0.w += __shfl_xor_sync(FULL, a0.w, m);
    }

    // ---- Phase 3: broadcast pooled vector via shuffles, fused tiny GEMM ----
    const float inv = (cnt > 0) ? (1.0f / (float)cnt) : 0.0f;
    const float p0 = __shfl_sync(FULL, a0.x, 0) * inv;
    const float p1 = __shfl_sync(FULL, a0.y, 0) * inv;
    const float p2 = __shfl_sync(FULL, a0.z, 0) * inv;
    const float p3 = __shfl_sync(FULL, a0.w, 0) * inv;
    const float p4 = __shfl_sync(FULL, a0.x, 1) * inv;
    const float p5 = __shfl_sync(FULL, a0.y, 1) * inv;
    const float p6 = __shfl_sync(FULL, a0.z, 1) * inv;
    const float p7 = __shfl_sync(FULL, a0.w, 1) * inv;

    if (lane < N_CLASSES) {
        const float* w = W + lane * D_FEAT;
        float r = __ldg(&b[lane]);
        r += p0 * __ldg(&w[0]) + p1 * __ldg(&w[1]) + p2 * __ldg(&w[2]) + p3 * __ldg(&w[3]);
        r += p4 * __ldg(&w[4]) + p5 * __ldg(&w[5]) + p6 * __ldg(&w[6]) + p7 * __ldg(&w[7]);
        out[g * N_CLASSES + lane] = r;
    }
}

extern "C" void kernel_launch(void* const* d_in, const int* in_sizes, int n_in,
                              void* d_out, int out_size) {
    // Bind inputs by element count (robust to metadata ordering):
    //   x: 32,000,000 f32 | batch_ids: 4,000,000 | W: 80 | b: 10
    const float* x   = nullptr;
    const void*  ids = nullptr;
    const float* W   = nullptr;
    const float* b   = nullptr;
    for (int i = 0; i < n_in; i++) {
        switch (in_sizes[i]) {
            case N_NODES * D_FEAT:   x   = (const float*)d_in[i]; break;
            case N_NODES:            ids = d_in[i];               break;
            case N_CLASSES * D_FEAT: W   = (const float*)d_in[i]; break;
            case N_CLASSES:          b   = (const float*)d_in[i]; break;
            default: break; // input_ids / attention_mask: unused
        }
    }
    float* out = (float*)d_out;

    fused_pool_gemm_kernel<<<N_BLOCKS, 256>>>(
        (const float4*)x, (const int*)ids, W, b, out);
}